// round 14
// baseline (speedup 1.0000x reference)
#include <cuda_runtime.h>

#define BB   8
#define DIMM 1024
#define TQ   2048
#define CDD  128
#define KK   1024
#define QQ   8
#define BT   (BB*TQ)   // 16384

// ---- scratch (device globals) ----
__device__ float g_resid[BB*DIMM*TQ];            // 64 MB residual [b][d][t]
__device__ float g_hp[2][CDD*BT];                // 16 MB h partials (d-split halves) [c][bt]
__device__ float g_cT[CDD*BT];                   // 8 MB gathered codes [c][bt]
__device__ float g_et[QQ*CDD*KK];                // 4 MB E transposed [q][c][k]
__device__ unsigned long long g_part[4*BT];      // per-split argmin packs
__device__ float g_e2[QQ*KK];                    // ||E_k||^2

// ---- packed f32x2 helpers ----
static __device__ __forceinline__ unsigned long long pk2(float v) {
    unsigned long long r; unsigned int u = __float_as_uint(v);
    asm("mov.b64 %0, {%1, %1};" : "=l"(r) : "r"(u));
    return r;
}
static __device__ __forceinline__ void fma2(unsigned long long& d,
                                            unsigned long long a, unsigned long long b) {
    asm("fma.rn.f32x2 %0, %1, %2, %0;" : "+l"(d) : "l"(a), "l"(b));
}
static __device__ __forceinline__ float2 unpk2(unsigned long long v) {
    unsigned int lo, hi;
    asm("mov.b64 {%0, %1}, %2;" : "=r"(lo), "=r"(hi) : "l"(v));
    float2 f; f.x = __uint_as_float(lo); f.y = __uint_as_float(hi);
    return f;
}
static __device__ __forceinline__ void cpa16(void* s, const void* g) {
    unsigned int sa = (unsigned int)__cvta_generic_to_shared(s);
    asm volatile("cp.async.cg.shared.global [%0], [%1], 16;" :: "r"(sa), "l"(g));
}
static __device__ __forceinline__ float4 ldg4(const float* p) {
    return __ldg((const float4*)p);
}
#define CP_COMMIT asm volatile("cp.async.commit_group;")
#define CP_WAIT0  asm volatile("cp.async.wait_group 0;")

// 8 scalar rows (S0,S1 float4) x 8 packed lanes (v0,v1 ulonglong2) -> 32 FFMA2
#define FMA2_ROW(i, s) { unsigned long long p = pk2(s); \
    fma2(acc[i][0], p, v0.x); fma2(acc[i][1], p, v0.y); \
    fma2(acc[i][2], p, v1.x); fma2(acc[i][3], p, v1.y); }
#define MICRO8(S0, S1) do { \
    FMA2_ROW(0, S0.x); FMA2_ROW(1, S0.y); FMA2_ROW(2, S0.z); FMA2_ROW(3, S0.w); \
    FMA2_ROW(4, S1.x); FMA2_ROW(5, S1.y); FMA2_ROW(6, S1.z); FMA2_ROW(7, S1.w); } while (0)

// ---- per-code squared norms ----
__global__ void k_e2(const float* __restrict__ E) {
    int row  = blockIdx.x * (blockDim.x >> 5) + (threadIdx.x >> 5);
    int lane = threadIdx.x & 31;
    if (row >= QQ * KK) return;
    const float* e = E + (size_t)row * CDD;
    float4 v = *(const float4*)(e + lane * 4);
    float s = v.x*v.x + v.y*v.y + v.z*v.z + v.w*v.w;
    #pragma unroll
    for (int o = 16; o; o >>= 1) s += __shfl_xor_sync(0xffffffffu, s, o);
    if (lane == 0) g_e2[row] = s;
}

// ---- E transpose: g_et[q][c][k] = E[q][k][c] ----
__global__ void k_et(const float* __restrict__ E) {
    __shared__ float tile[32][33];
    int q = blockIdx.z, k0 = blockIdx.x * 32, c0 = blockIdx.y * 32;
    int tx = threadIdx.x & 31, ty = threadIdx.x >> 5;
    const float* Eq = E + (size_t)q * KK * CDD;
    #pragma unroll
    for (int i = 0; i < 4; i++)
        tile[ty + 8*i][tx] = Eq[(size_t)(k0 + ty + 8*i) * CDD + c0 + tx];
    __syncthreads();
    float* o = g_et + (size_t)q * CDD * KK;
    #pragma unroll
    for (int i = 0; i < 4; i++)
        o[(size_t)(c0 + ty + 8*i) * KK + k0 + tx] = tile[tx][ty + 8*i];
}

// ---- kernel 1: h partial: g_hp[ds][c][bt] = sum_{d in half ds} src[b,d,t]*Win[d,c] ----
// grid (32 t-tiles, 8 b, 2 d-halves), 128 thr. A via cp.async, W via __ldg.
#define PROJ_PREFETCH_A(bufi, d0) do { \
    _Pragma("unroll") for (int j = 0; j < 2; j++) { int ix = tid + j*128; \
        int dd = ix >> 4, t4 = (ix & 15) * 4; \
        cpa16(&As[bufi][dd][t4], rb + (size_t)((d0) + dd) * TQ + t4); } \
    CP_COMMIT; } while (0)

__global__ void __launch_bounds__(128) k_proj(const float* __restrict__ emb,
                                              const float* __restrict__ Win,
                                              int q, int use_emb) {
    __shared__ __align__(16) float As[2][16][64];    // [d][t] 8KB
    int t0 = blockIdx.x * 64, b = blockIdx.y, ds = blockIdx.z;
    int tid = threadIdx.x, txt = tid & 7, tyc = tid >> 3;  // t = txt*8, c = tyc*8
    int bt0 = b * TQ + t0;
    const float* src = use_emb ? emb : (const float*)g_resid;
    const float* rb = src + (size_t)b * DIMM * TQ + (size_t)ds * 512 * TQ + t0;
    const float* Wq = Win + (size_t)q * DIMM * CDD + (size_t)ds * 512 * CDD;

    PROJ_PREFETCH_A(0, 0);
    unsigned long long acc[8][4];
    #pragma unroll
    for (int i = 0; i < 8; i++)
        #pragma unroll
        for (int p = 0; p < 4; p++) acc[i][p] = 0ull;

    int buf = 0;
    for (int kt = 0; kt < 32; kt++) {
        CP_WAIT0; __syncthreads();
        if (kt + 1 < 32) PROJ_PREFETCH_A(buf ^ 1, (kt + 1) * 16);
        const float* wrow = Wq + (size_t)(kt * 16) * CDD + tyc * 8;
        #pragma unroll 4
        for (int dd = 0; dd < 16; dd++) {
            float4 w0 = ldg4(wrow + (size_t)dd * CDD);
            float4 w1 = ldg4(wrow + (size_t)dd * CDD + 4);
            ulonglong2 v0 = *(const ulonglong2*)&As[buf][dd][txt * 8];
            ulonglong2 v1 = *(const ulonglong2*)&As[buf][dd][txt * 8 + 4];
            MICRO8(w0, w1);
        }
        buf ^= 1;
    }
    float* hb = g_hp[ds];
    #pragma unroll
    for (int ci = 0; ci < 8; ci++) {
        int c = tyc * 8 + ci;
        float2 u0 = unpk2(acc[ci][0]), u1 = unpk2(acc[ci][1]);
        float2 u2 = unpk2(acc[ci][2]), u3 = unpk2(acc[ci][3]);
        float* hp = hb + (size_t)c * BT + bt0 + txt * 8;
        *(float4*)hp       = make_float4(u0.x, u0.y, u1.x, u1.y);
        *(float4*)(hp + 4) = make_float4(u2.x, u2.y, u3.x, u3.y);
    }
}

// ---- kernel 2: argmin_k ( e2[k] - 2 h.E_k ), 4-way code split ----
// grid (256, 4), 128 thr. h in smem (loaded once); E via __ldg register pipeline.
__global__ void __launch_bounds__(128) k_dist(const float* __restrict__ bin, int q) {
    __shared__ __align__(16) float hsT[128][64];    // 32KB
    __shared__ unsigned long long red[64][16];      // 8KB
    int r0 = blockIdx.x * 64, nbase = blockIdx.y * 256;
    int tid = threadIdx.x, txt = tid & 7, tyk = tid >> 3;
    const float* etq = g_et + (size_t)q * CDD * KK;
    const float* e2q = g_e2 + q * KK;
    const float* binq = bin + q * CDD;

    // h = hp0 + hp1 + bin (merge d-split partials), once
    const float* hp0 = g_hp[0];
    const float* hp1 = g_hp[1];
    #pragma unroll
    for (int j = 0; j < 16; j++) {
        int ix = tid + j * 128; int c = ix >> 4, t4 = (ix & 15) * 4;
        float4 a = *(const float4*)(hp0 + (size_t)c * BT + r0 + t4);
        float4 bq = *(const float4*)(hp1 + (size_t)c * BT + r0 + t4);
        float bi = binq[c];
        *(float4*)&hsT[c][t4] = make_float4(a.x + bq.x + bi, a.y + bq.y + bi,
                                            a.z + bq.z + bi, a.w + bq.w + bi);
    }
    __syncthreads();

    float minv[8]; int mini[8];
    #pragma unroll
    for (int j = 0; j < 8; j++) { minv[j] = 3.0e38f; mini[j] = 0; }

    for (int nt = 0; nt < 2; nt++) {
        int n0 = nbase + nt * 128;
        const float* ep = etq + n0 + tyk * 8;    // row stride KK over c
        unsigned long long acc[8][4];
        #pragma unroll
        for (int i = 0; i < 8; i++)
            #pragma unroll
            for (int p = 0; p < 4; p++) acc[i][p] = 0ull;

        // register pipeline: current pair (cc, cc+1), prefetch pair (cc+2, cc+3)
        float4 ca0 = ldg4(ep),      ca1 = ldg4(ep + 4);
        float4 cb0 = ldg4(ep + KK), cb1 = ldg4(ep + KK + 4);
        #pragma unroll 4
        for (int cc = 0; cc < 128; cc += 2) {
            float4 na0, na1, nb0, nb1;
            if (cc < 126) {
                const float* p2 = ep + (size_t)(cc + 2) * KK;
                na0 = ldg4(p2);      na1 = ldg4(p2 + 4);
                nb0 = ldg4(p2 + KK); nb1 = ldg4(p2 + KK + 4);
            }
            {
                ulonglong2 v0 = *(const ulonglong2*)&hsT[cc][txt * 8];
                ulonglong2 v1 = *(const ulonglong2*)&hsT[cc][txt * 8 + 4];
                MICRO8(ca0, ca1);
            }
            {
                ulonglong2 v0 = *(const ulonglong2*)&hsT[cc + 1][txt * 8];
                ulonglong2 v1 = *(const ulonglong2*)&hsT[cc + 1][txt * 8 + 4];
                MICRO8(cb0, cb1);
            }
            ca0 = na0; ca1 = na1; cb0 = nb0; cb1 = nb1;
        }
        // epilogue argmin for this n-tile (identical order to previous rounds)
        int kb = n0 + tyk * 8;
        float4 ev0 = ldg4(e2q + kb), ev1 = ldg4(e2q + kb + 4);
        float e2r[8] = {ev0.x, ev0.y, ev0.z, ev0.w, ev1.x, ev1.y, ev1.z, ev1.w};
        #pragma unroll
        for (int ki = 0; ki < 8; ki++) {
            float ev = e2r[ki];
            int k = kb + ki;
            #pragma unroll
            for (int tp = 0; tp < 4; tp++) {
                float2 u = unpk2(acc[ki][tp]);
                float da = ev - 2.0f * u.x;
                float db = ev - 2.0f * u.y;
                if (da < minv[tp*2])     { minv[tp*2]     = da; mini[tp*2]     = k; }
                if (db < minv[tp*2 + 1]) { minv[tp*2 + 1] = db; mini[tp*2 + 1] = k; }
            }
        }
    }
    #pragma unroll
    for (int j = 0; j < 8; j++) {
        unsigned int bbits = __float_as_uint(minv[j]);
        bbits = (bbits & 0x80000000u) ? ~bbits : (bbits | 0x80000000u);
        red[txt * 8 + j][tyk] = ((unsigned long long)bbits << 32) | (unsigned int)mini[j];
    }
    __syncthreads();
    if (tid < 64) {
        unsigned long long m = red[tid][0];
        #pragma unroll
        for (int x = 1; x < 16; x++) { unsigned long long v = red[tid][x]; if (v < m) m = v; }
        g_part[(size_t)blockIdx.y * BT + r0 + tid] = m;
    }
}

// ---- kernel 2.5: merge splits + gather: g_cT[c][bt] = E_q[idx[bt]][c] ----
__global__ void __launch_bounds__(128) k_gather(const float* __restrict__ E, int q) {
    __shared__ float sT[128][65];
    __shared__ int sidx[64];
    int bt0 = blockIdx.x * 64;
    int tid = threadIdx.x;
    if (tid < 64) {
        unsigned long long m = g_part[bt0 + tid];
        #pragma unroll
        for (int s = 1; s < 4; s++) {
            unsigned long long v = g_part[(size_t)s * BT + bt0 + tid];
            if (v < m) m = v;
        }
        sidx[tid] = (int)(unsigned int)(m & 0xFFFFFFFFull);
    }
    __syncthreads();
    const float* Eq = E + (size_t)q * KK * CDD;
    #pragma unroll
    for (int j = 0; j < 16; j++) {
        int ch = tid + j * 128; int tt = ch >> 5, c4 = ch & 31;
        float4 v = *(const float4*)(Eq + (size_t)sidx[tt] * CDD + c4 * 4);
        sT[c4*4][tt] = v.x; sT[c4*4+1][tt] = v.y; sT[c4*4+2][tt] = v.z; sT[c4*4+3][tt] = v.w;
    }
    __syncthreads();
    #pragma unroll
    for (int j = 0; j < 16; j++) {
        int ch = tid + j * 128; int c = ch >> 4, t4 = (ch & 15) * 4;
        *(float4*)(g_cT + (size_t)c * BT + bt0 + t4) =
            make_float4(sT[c][t4], sT[c][t4+1], sT[c][t4+2], sT[c][t4+3]);
    }
}

// ---- kernel 3: qv = g_cT.Wout + bout; resid update or final out ----
// grid (32 t-tiles, 8 d-blk, 8 b), 128 thr. cT via cp.async, W via __ldg.
#define DEC_PREFETCH_A(bufi, c0) do { \
    _Pragma("unroll") for (int j = 0; j < 2; j++) { int ix = tid + j*128; \
        int cc = ix >> 4, t4 = (ix & 15) * 4; \
        cpa16(&As[bufi][cc][t4], g_cT + (size_t)((c0) + cc) * BT + bt0 + t4); } \
    CP_COMMIT; } while (0)

__global__ void __launch_bounds__(128) k_dec(const float* __restrict__ Wout,
                                             const float* __restrict__ bout, int q,
                                             const float* __restrict__ emb,
                                             float* __restrict__ out,
                                             int use_emb, int is_final) {
    __shared__ __align__(16) float As[2][16][64];    // [c][t] 8KB
    int t0 = blockIdx.x * 64, d0 = blockIdx.y * 128, b = blockIdx.z;
    int tid = threadIdx.x, txt = tid & 7, tyd = tid >> 3;
    int bt0 = b * TQ + t0;
    const float* rsrc = use_emb ? emb : (const float*)g_resid;
    const float* Wq = Wout + (size_t)q * CDD * DIMM + d0;

    DEC_PREFETCH_A(0, 0);
    unsigned long long acc[8][4];
    #pragma unroll
    for (int i = 0; i < 8; i++)
        #pragma unroll
        for (int p = 0; p < 4; p++) acc[i][p] = 0ull;

    int buf = 0;
    for (int kt = 0; kt < 8; kt++) {
        CP_WAIT0; __syncthreads();
        if (kt + 1 < 8) DEC_PREFETCH_A(buf ^ 1, (kt + 1) * 16);
        const float* wrow = Wq + (size_t)(kt * 16) * DIMM + tyd * 8;
        #pragma unroll 4
        for (int cc = 0; cc < 16; cc++) {
            float4 w0 = ldg4(wrow + (size_t)cc * DIMM);
            float4 w1 = ldg4(wrow + (size_t)cc * DIMM + 4);
            ulonglong2 v0 = *(const ulonglong2*)&As[buf][cc][txt * 8];
            ulonglong2 v1 = *(const ulonglong2*)&As[buf][cc][txt * 8 + 4];
            MICRO8(w0, w1);
        }
        buf ^= 1;
    }
    #pragma unroll
    for (int di = 0; di < 8; di++) {
        int d = d0 + tyd * 8 + di;
        float bo = bout[q * DIMM + d];
        float2 u0 = unpk2(acc[di][0]), u1 = unpk2(acc[di][1]);
        float2 u2 = unpk2(acc[di][2]), u3 = unpk2(acc[di][3]);
        size_t off = ((size_t)b * DIMM + d) * TQ + t0 + txt * 8;
        float4 q0 = make_float4(u0.x + bo, u0.y + bo, u1.x + bo, u1.y + bo);
        float4 q1 = make_float4(u2.x + bo, u2.y + bo, u3.x + bo, u3.y + bo);
        float4 r0v = *(const float4*)(rsrc + off);
        float4 r1v = *(const float4*)(rsrc + off + 4);
        if (is_final) {   // out = emb - resid + qv
            float4 e0 = *(const float4*)(emb + off);
            float4 e1 = *(const float4*)(emb + off + 4);
            *(float4*)(out + off)     = make_float4(e0.x - r0v.x + q0.x, e0.y - r0v.y + q0.y,
                                                    e0.z - r0v.z + q0.z, e0.w - r0v.w + q0.w);
            *(float4*)(out + off + 4) = make_float4(e1.x - r1v.x + q1.x, e1.y - r1v.y + q1.y,
                                                    e1.z - r1v.z + q1.z, e1.w - r1v.w + q1.w);
        } else {          // resid = rsrc - qv
            *(float4*)(g_resid + off)     = make_float4(r0v.x - q0.x, r0v.y - q0.y,
                                                        r0v.z - q0.z, r0v.w - q0.w);
            *(float4*)(g_resid + off + 4) = make_float4(r1v.x - q1.x, r1v.y - q1.y,
                                                        r1v.z - q1.z, r1v.w - q1.w);
        }
    }
}

extern "C" void kernel_launch(void* const* d_in, const int* in_sizes, int n_in,
                              void* d_out, int out_size) {
    const float* emb  = (const float*)d_in[0];
    const float* Win  = (const float*)d_in[1];
    const float* bin  = (const float*)d_in[2];
    const float* Wout = (const float*)d_in[3];
    const float* bout = (const float*)d_in[4];
    const float* E    = (const float*)d_in[5];
    float* out = (float*)d_out;

    k_et<<<dim3(KK / 32, CDD / 32, QQ), 256>>>(E);
    k_e2<<<(QQ * KK) / 8, 256>>>(E);
    for (int q = 0; q < QQ; q++) {
        int use_emb = (q == 0) ? 1 : 0;
        k_proj<<<dim3(TQ / 64, BB, 2), 128>>>(emb, Win, q, use_emb);
        k_dist<<<dim3(BT / 64, 4), 128>>>(bin, q);
        k_gather<<<BT / 64, 128>>>(E, q);
        k_dec<<<dim3(TQ / 64, DIMM / 128, BB), 128>>>(
            Wout, bout, q, emb, out, use_emb, (q == QQ - 1) ? 1 : 0);
    }
}